// round 7
// baseline (speedup 1.0000x reference)
#include <cuda_runtime.h>
#include <cuda_bf16.h>
#include <cstdint>

#define NN 200000
#define EE 640000
#define SB 512
#define NBLK 391   // ceil(NN / SB)

// ---------------- persistent device scratch (no allocations allowed) ----------------
// h buffers: packed bf16, 64 uint32 per 128-feat row (32-feat rows use stride 16)
__device__ uint32_t g_hA[(size_t)NN * 64];
__device__ uint32_t g_hB[(size_t)NN * 64];
__device__ float    g_dis[NN];
__device__ int      g_cnt[NN];
__device__ int      g_fill[NN];
__device__ int      g_row[NN + 1];
__device__ int      g_col[EE];
__device__ float    g_en[EE];
__device__ int      g_part[SB];
__device__ int      g_is64;

// ---------------- helpers ----------------
__device__ __forceinline__ uint32_t f2tf32(float f) {
    uint32_t u;
    asm("cvt.rna.tf32.f32 %0, %1;" : "=r"(u) : "f"(f));
    return u;
}

__device__ __forceinline__ uint32_t pack_bf16(float lo, float hi) {
    __nv_bfloat162 h = __floats2bfloat162_rn(lo, hi);   // .x = lo (low 16 bits)
    return *reinterpret_cast<uint32_t*>(&h);
}

__device__ __forceinline__ float2 unpack_bf16(uint32_t u) {
    __nv_bfloat162 h = *reinterpret_cast<__nv_bfloat162*>(&u);
    return __bfloat1622float2(h);                        // .x = low half
}

__device__ __forceinline__ void mma_tf32(float c[4],
                                         uint32_t a0, uint32_t a1, uint32_t a2, uint32_t a3,
                                         uint32_t b0, uint32_t b1) {
    asm volatile(
        "mma.sync.aligned.m16n8k8.row.col.f32.tf32.tf32.f32 "
        "{%0,%1,%2,%3}, {%4,%5,%6,%7}, {%8,%9}, {%0,%1,%2,%3};\n"
        : "+f"(c[0]), "+f"(c[1]), "+f"(c[2]), "+f"(c[3])
        : "r"(a0), "r"(a1), "r"(a2), "r"(a3), "r"(b0), "r"(b1));
}

// ---------------- edge dtype probe (int64 vs int32) ----------------
__device__ __forceinline__ int edge_at(const void* ei, int idx) {
    int v;
    if (g_is64) v = (int)((const long long*)ei)[idx];
    else        v = ((const int*)ei)[idx];
    return min(max(v, 0), NN - 1);
}

// ---------------- CSR build ----------------
__global__ void k_zero(const void* ei) {
    int i = blockIdx.x * blockDim.x + threadIdx.x;
    if (i < NN) { g_cnt[i] = 0; g_fill[i] = 0; }
    if (i == 0) {   // dtype probe merged here
        const long long* p = (const long long*)ei;
        int ok = 1;
        #pragma unroll
        for (int j = 0; j < 4; j++) {
            long long v = p[j];
            if (v < 0 || v >= NN) ok = 0;
        }
        g_is64 = ok;
    }
}

__global__ void k_count(const void* __restrict__ ei) {
    int e = blockIdx.x * blockDim.x + threadIdx.x;
    if (e < EE) atomicAdd(&g_cnt[edge_at(ei, EE + e)], 1);
}

__global__ void k_scanA() {
    __shared__ int tmp[SB];
    int tid = threadIdx.x;
    int i = blockIdx.x * SB + tid;
    int v = (i < NN) ? g_cnt[i] : 0;
    tmp[tid] = v; __syncthreads();
    for (int off = 1; off < SB; off <<= 1) {
        int t = (tid >= off) ? tmp[tid - off] : 0;
        __syncthreads();
        if (tid >= off) tmp[tid] += t;
        __syncthreads();
    }
    if (i < NN) g_row[i + 1] = tmp[tid];
    if (tid == SB - 1) g_part[blockIdx.x] = tmp[tid];
}

__global__ void k_scanB() {
    __shared__ int tmp[SB];
    int tid = threadIdx.x;
    int v = (tid < NBLK) ? g_part[tid] : 0;
    tmp[tid] = v; __syncthreads();
    for (int off = 1; off < SB; off <<= 1) {
        int t = (tid >= off) ? tmp[tid - off] : 0;
        __syncthreads();
        if (tid >= off) tmp[tid] += t;
        __syncthreads();
    }
    if (tid < NBLK) g_part[tid] = tmp[tid] - v;   // exclusive block offsets
}

__global__ void k_scanC() {   // also computes g_dis (merged)
    int i = blockIdx.x * blockDim.x + threadIdx.x;
    if (i < NN) {
        g_row[i + 1] += g_part[i / SB];
        if (i == 0) g_row[0] = 0;
        g_dis[i] = rsqrtf((float)g_cnt[i] + 1.0f);
    }
}

__global__ void k_fill(const void* __restrict__ ei) {
    int e = blockIdx.x * blockDim.x + threadIdx.x;
    if (e < EE) {
        int d = edge_at(ei, EE + e);
        int s = edge_at(ei, e);
        int p = g_row[d] + atomicAdd(&g_fill[d], 1);
        g_col[p] = s;
        g_en[p] = g_dis[s] * g_dis[d];
    }
}

// ---------------- layer 1: aggregate x (2 feats) then [N,2]@[2,32]+b1, relu -> g_hB (bf16) ----------------
__global__ void k_layer1(const float* __restrict__ x,
                         const float* __restrict__ W1,
                         const float* __restrict__ b1) {
    __shared__ float w[64], bb[32];
    if (threadIdx.x < 64) w[threadIdx.x] = W1[threadIdx.x];
    if (threadIdx.x < 32) bb[threadIdx.x] = b1[threadIdx.x];
    __syncthreads();
    int v = blockIdx.x * blockDim.x + threadIdx.x;
    if (v >= NN) return;
    float dv = g_dis[v];
    float a0 = dv * dv * x[2 * v];
    float a1 = dv * dv * x[2 * v + 1];
    int e0 = g_row[v], e1 = g_row[v + 1];
    for (int e = e0; e < e1; e++) {
        int s = g_col[e];
        float nm = g_en[e];
        a0 += nm * x[2 * s];
        a1 += nm * x[2 * s + 1];
    }
    uint32_t* out = &g_hB[(size_t)v * 16];
    #pragma unroll
    for (int j = 0; j < 16; j++) {
        float r0 = fmaxf(a0 * w[2 * j]     + a1 * w[32 + 2 * j]     + bb[2 * j],     0.0f);
        float r1 = fmaxf(a0 * w[2 * j + 1] + a1 * w[32 + 2 * j + 1] + bb[2 * j + 1], 0.0f);
        out[j] = pack_bf16(r0, r1);
    }
}

// ---------------- fused layer: aggregate 64 bf16 rows -> smem (tf32, row-major), then tf32 MMA ----------------
// 256 threads, 3125 blocks (64 nodes each).
// As stride FIN+4: phase-1 STS.128 conflict-free (consecutive lanes, 16B aligned);
// phase-2 fragment loads bank = (4*group + tig) mod 32 -> all 32 distinct.
// Ws stride 136: bank 8k+n distinct -> conflict-free.
template <int FIN, bool IN_A>
__global__ void __launch_bounds__(256, 2) k_fused(const float* __restrict__ W,
                                                  const float* __restrict__ b) {
    constexpr int WS  = 136;
    constexpr int AS2 = FIN + 4;
    extern __shared__ float smem[];
    float*    Ws = smem;                              // [FIN][WS], tf32 bits
    uint32_t* As = (uint32_t*)(smem + FIN * WS);      // [64][AS2], tf32 bits, row-major
    const uint32_t* hin  = IN_A ? g_hA : g_hB;
    uint32_t*       hout = IN_A ? g_hB : g_hA;

    const int tid  = threadIdx.x;
    const int wid  = tid >> 5;
    const int lane = tid & 31;

    // ---- load W into shared, converting to tf32 ----
    for (int idx4 = tid; idx4 < FIN * 32; idx4 += 256) {
        int k  = idx4 >> 5;
        int n4 = idx4 & 31;
        float4 wv = ((const float4*)W)[idx4];
        uint4 t;
        t.x = f2tf32(wv.x); t.y = f2tf32(wv.y);
        t.z = f2tf32(wv.z); t.w = f2tf32(wv.w);
        *(uint4*)&Ws[k * WS + n4 * 4] = t;
    }

    // ---- phase 1: aggregate 8 nodes per warp into As (row-major, tf32 bits) ----
    if (FIN == 128) {
        #pragma unroll 1
        for (int n = 0; n < 8; n++) {
            int vloc = wid * 8 + n;
            int v = blockIdx.x * 64 + vloc;
            float dv = g_dis[v];
            float sn = dv * dv;
            uint2 u = __ldg((const uint2*)(hin + (size_t)v * 64) + lane);
            float2 p0 = unpack_bf16(u.x), p1 = unpack_bf16(u.y);
            float a0 = sn * p0.x, a1 = sn * p0.y, a2 = sn * p1.x, a3 = sn * p1.y;

            int e  = g_row[v];
            int e1 = g_row[v + 1];
            for (; e + 3 < e1; e += 4) {
                int   s0 = g_col[e],   s1 = g_col[e+1], s2 = g_col[e+2], s3 = g_col[e+3];
                float m0 = g_en[e],    m1 = g_en[e+1],  m2 = g_en[e+2],  m3 = g_en[e+3];
                uint2 u0 = __ldg((const uint2*)(hin + (size_t)s0 * 64) + lane);
                uint2 u1 = __ldg((const uint2*)(hin + (size_t)s1 * 64) + lane);
                uint2 u2 = __ldg((const uint2*)(hin + (size_t)s2 * 64) + lane);
                uint2 u3 = __ldg((const uint2*)(hin + (size_t)s3 * 64) + lane);
                float2 q;
                q = unpack_bf16(u0.x); a0 += m0*q.x; a1 += m0*q.y;
                q = unpack_bf16(u0.y); a2 += m0*q.x; a3 += m0*q.y;
                q = unpack_bf16(u1.x); a0 += m1*q.x; a1 += m1*q.y;
                q = unpack_bf16(u1.y); a2 += m1*q.x; a3 += m1*q.y;
                q = unpack_bf16(u2.x); a0 += m2*q.x; a1 += m2*q.y;
                q = unpack_bf16(u2.y); a2 += m2*q.x; a3 += m2*q.y;
                q = unpack_bf16(u3.x); a0 += m3*q.x; a1 += m3*q.y;
                q = unpack_bf16(u3.y); a2 += m3*q.x; a3 += m3*q.y;
            }
            for (; e < e1; e++) {
                int   s0 = g_col[e];
                float m0 = g_en[e];
                uint2 u0 = __ldg((const uint2*)(hin + (size_t)s0 * 64) + lane);
                float2 q;
                q = unpack_bf16(u0.x); a0 += m0*q.x; a1 += m0*q.y;
                q = unpack_bf16(u0.y); a2 += m0*q.x; a3 += m0*q.y;
            }

            uint4 t;
            t.x = f2tf32(a0); t.y = f2tf32(a1); t.z = f2tf32(a2); t.w = f2tf32(a3);
            *(uint4*)&As[vloc * AS2 + 4 * lane] = t;   // 16B aligned: 528*vloc + 16*lane
        }
    } else { // FIN == 32: lanes 0..15 active, 2 features per lane
        #pragma unroll 1
        for (int n = 0; n < 8; n++) {
            int vloc = wid * 8 + n;
            int v = blockIdx.x * 64 + vloc;
            if (lane < 16) {
                float dv = g_dis[v];
                float sn = dv * dv;
                float2 p = unpack_bf16(__ldg(hin + (size_t)v * 16 + lane));
                float a0 = sn * p.x, a1 = sn * p.y;

                int e  = g_row[v];
                int e1 = g_row[v + 1];
                for (; e + 3 < e1; e += 4) {
                    int   s0 = g_col[e],   s1 = g_col[e+1], s2 = g_col[e+2], s3 = g_col[e+3];
                    float m0 = g_en[e],    m1 = g_en[e+1],  m2 = g_en[e+2],  m3 = g_en[e+3];
                    float2 q0 = unpack_bf16(__ldg(hin + (size_t)s0 * 16 + lane));
                    float2 q1 = unpack_bf16(__ldg(hin + (size_t)s1 * 16 + lane));
                    float2 q2 = unpack_bf16(__ldg(hin + (size_t)s2 * 16 + lane));
                    float2 q3 = unpack_bf16(__ldg(hin + (size_t)s3 * 16 + lane));
                    a0 += m0*q0.x + m1*q1.x + m2*q2.x + m3*q3.x;
                    a1 += m0*q0.y + m1*q1.y + m2*q2.y + m3*q3.y;
                }
                for (; e < e1; e++) {
                    float2 q = unpack_bf16(__ldg(hin + (size_t)g_col[e] * 16 + lane));
                    a0 += g_en[e] * q.x;
                    a1 += g_en[e] * q.y;
                }

                As[vloc * AS2 + 2 * lane]     = f2tf32(a0);
                As[vloc * AS2 + 2 * lane + 1] = f2tf32(a1);
            }
        }
    }
    __syncthreads();

    // ---- phase 2: tf32 MMA, warp tile 32x32 (2 mi x 4 ni of m16n8k8) ----
    const uint32_t* WsU = (const uint32_t*)Ws;
    const int rowt = wid & 1;          // 2 row tiles of 32
    const int colt = wid >> 1;         // 4 col tiles of 32
    const int r_base = rowt * 32;
    const int n_base = colt * 32;
    const int group = lane >> 2;       // 0..7
    const int tig   = lane & 3;        // 0..3

    float C[2][4][4];
    #pragma unroll
    for (int mi = 0; mi < 2; mi++)
        #pragma unroll
        for (int ni = 0; ni < 4; ni++)
            #pragma unroll
            for (int j = 0; j < 4; j++) C[mi][ni][j] = 0.0f;

    #pragma unroll
    for (int k0 = 0; k0 < FIN; k0 += 8) {
        uint32_t a[2][4];
        #pragma unroll
        for (int mi = 0; mi < 2; mi++) {
            int r0 = r_base + mi * 16 + group;
            a[mi][0] = As[r0 * AS2 + k0 + tig];
            a[mi][1] = As[(r0 + 8) * AS2 + k0 + tig];
            a[mi][2] = As[r0 * AS2 + k0 + tig + 4];
            a[mi][3] = As[(r0 + 8) * AS2 + k0 + tig + 4];
        }
        #pragma unroll
        for (int ni = 0; ni < 4; ni++) {
            int nc = n_base + ni * 8 + group;
            uint32_t b0 = WsU[(k0 + tig) * WS + nc];
            uint32_t b1 = WsU[(k0 + tig + 4) * WS + nc];
            mma_tf32(C[0][ni], a[0][0], a[0][1], a[0][2], a[0][3], b0, b1);
            mma_tf32(C[1][ni], a[1][0], a[1][1], a[1][2], a[1][3], b0, b1);
        }
    }

    // ---- epilogue: bias + relu, pack to bf16x2 ----
    #pragma unroll
    for (int ni = 0; ni < 4; ni++) {
        int col = n_base + ni * 8 + 2 * tig;
        float2 bb = __ldg((const float2*)&b[col]);
        #pragma unroll
        for (int mi = 0; mi < 2; mi++) {
            int row0 = blockIdx.x * 64 + r_base + mi * 16 + group;
            float o00 = fmaxf(C[mi][ni][0] + bb.x, 0.0f);
            float o01 = fmaxf(C[mi][ni][1] + bb.y, 0.0f);
            float o10 = fmaxf(C[mi][ni][2] + bb.x, 0.0f);
            float o11 = fmaxf(C[mi][ni][3] + bb.y, 0.0f);
            hout[(size_t)row0 * 64 + (col >> 1)]       = pack_bf16(o00, o01);
            hout[(size_t)(row0 + 8) * 64 + (col >> 1)] = pack_bf16(o10, o11);
        }
    }
}

// ---------------- final: out = leakyrelu(h5 @ Wl + bl), one warp per node ----------------
__global__ void k_final(const float* __restrict__ Wl,
                        const float* __restrict__ bl,
                        float* __restrict__ out) {
    int warp = (blockIdx.x * blockDim.x + threadIdx.x) >> 5;   // exactly NN warps
    int lane = threadIdx.x & 31;
    uint2 u = __ldg((const uint2*)(g_hB + (size_t)warp * 64) + lane);
    float2 p0 = unpack_bf16(u.x), p1 = unpack_bf16(u.y);
    float4 w  = __ldg((const float4*)&Wl[lane * 4]);
    float s = p0.x * w.x + p0.y * w.y + p1.x * w.z + p1.y * w.w;
    #pragma unroll
    for (int off = 16; off; off >>= 1) s += __shfl_down_sync(0xFFFFFFFFu, s, off);
    if (lane == 0) {
        s += __ldg(bl);
        out[warp] = (s > 0.0f) ? s : 0.01f * s;
    }
}

// ---------------- launch ----------------
extern "C" void kernel_launch(void* const* d_in, const int* in_sizes, int n_in,
                              void* d_out, int out_size) {
    int ix = 0, ie = 1, iW1 = 2, ib1 = 3, iW2 = 4, ib2 = 5, iW3 = 6, ib3 = 7,
        iW4 = 8, ib4 = 9, iW5 = 10, ib5 = 11, iWl = 12, ibl = 13;
    if (n_in >= 14 && in_sizes[0] != 2 * NN) {
        if (in_sizes[0] == 64 && in_sizes[1] == 4096) {
            iW1 = 0; iW2 = 1; iW3 = 2; iW4 = 3; iW5 = 4; iWl = 5;
            ib1 = 6; ib2 = 7; ib3 = 8; ib4 = 9; ib5 = 10; ibl = 11;
            ie = 12; ix = 13;
        }
    }

    const float* x  = (const float*)d_in[ix];
    const void*  ei = d_in[ie];
    const float* W1 = (const float*)d_in[iW1];
    const float* b1 = (const float*)d_in[ib1];
    const float* W2 = (const float*)d_in[iW2];
    const float* b2 = (const float*)d_in[ib2];
    const float* W3 = (const float*)d_in[iW3];
    const float* b3 = (const float*)d_in[ib3];
    const float* W4 = (const float*)d_in[iW4];
    const float* b4 = (const float*)d_in[ib4];
    const float* W5 = (const float*)d_in[iW5];
    const float* b5 = (const float*)d_in[ib5];
    const float* Wl = (const float*)d_in[iWl];
    const float* bl = (const float*)d_in[ibl];
    float* out = (float*)d_out;

    const int sh32  = (32  * 136 + 64 * 36)  * 4;   // 26,624 B
    const int sh128 = (128 * 136 + 64 * 132) * 4;   // 103,424 B
    cudaFuncSetAttribute(k_fused<32,  false>, cudaFuncAttributeMaxDynamicSharedMemorySize, sh32);
    cudaFuncSetAttribute(k_fused<128, true >, cudaFuncAttributeMaxDynamicSharedMemorySize, sh128);
    cudaFuncSetAttribute(k_fused<128, false>, cudaFuncAttributeMaxDynamicSharedMemorySize, sh128);

    // CSR + norms (dtype probe merged into k_zero)
    k_zero <<<(NN + 255) / 256, 256>>>(ei);
    k_count<<<(EE + 255) / 256, 256>>>(ei);
    k_scanA<<<NBLK, SB>>>();
    k_scanB<<<1, SB>>>();
    k_scanC<<<(NN + 255) / 256, 256>>>();   // + g_dis
    k_fill <<<(EE + 255) / 256, 256>>>(ei);

    // layers: fused aggregate (bf16 gathers, fp32 accum) + tf32 MMA gemm (bf16 out)
    k_layer1<<<(NN + 255) / 256, 256>>>(x, W1, b1);            // x  -> hB [N,32] bf16
    k_fused<32,  false><<<3125, 256, sh32 >>>(W2, b2);         // hB -> hA [N,128] bf16
    k_fused<128, true ><<<3125, 256, sh128>>>(W3, b3);         // hA -> hB
    k_fused<128, false><<<3125, 256, sh128>>>(W4, b4);         // hB -> hA
    k_fused<128, true ><<<3125, 256, sh128>>>(W5, b5);         // hA -> hB

    k_final<<<NN / 8, 256>>>(Wl, bl, out);                     // 8 warps/block, exact
}

// round 8
// speedup vs baseline: 1.6450x; 1.6450x over previous
#include <cuda_runtime.h>
#include <cuda_fp16.h>
#include <cstdint>

#define NN 200000
#define EE 640000
#define SB 512
#define NBLK 391   // ceil(NN / SB)

// ---------------- persistent device scratch (no allocations allowed) ----------------
// h buffers: packed fp16, 64 uint32 per 128-feat row (32-feat rows use stride 16)
__device__ uint32_t g_hA[(size_t)NN * 64];
__device__ uint32_t g_hB[(size_t)NN * 64];
__device__ uint32_t g_hC[(size_t)NN * 64];    // aggregated rows, fp16 packed
__device__ uint32_t g_Wt[4][128 * 64];        // W2..W5 as fp16, transposed [n][k-pairs]
__device__ float    g_dis[NN];
__device__ int      g_cnt[NN];
__device__ int      g_fill[NN];
__device__ int      g_row[NN + 1];
__device__ int      g_col[EE];
__device__ float    g_en[EE];
__device__ int      g_part[SB];
__device__ int      g_is64;

// ---------------- helpers ----------------
__device__ __forceinline__ uint32_t pack_f16(float lo, float hi) {
    __half2 h = __floats2half2_rn(lo, hi);               // .x = lo (low 16 bits)
    return *reinterpret_cast<uint32_t*>(&h);
}

__device__ __forceinline__ float2 unpack_f16(uint32_t u) {
    __half2 h = *reinterpret_cast<__half2*>(&u);
    return __half22float2(h);                            // .x = low half
}

__device__ __forceinline__ void mma_f16(float c[4],
                                        uint32_t a0, uint32_t a1, uint32_t a2, uint32_t a3,
                                        uint32_t b0, uint32_t b1) {
    asm volatile(
        "mma.sync.aligned.m16n8k16.row.col.f32.f16.f16.f32 "
        "{%0,%1,%2,%3}, {%4,%5,%6,%7}, {%8,%9}, {%0,%1,%2,%3};\n"
        : "+f"(c[0]), "+f"(c[1]), "+f"(c[2]), "+f"(c[3])
        : "r"(a0), "r"(a1), "r"(a2), "r"(a3), "r"(b0), "r"(b1));
}

// ---------------- edge dtype probe (int64 vs int32) ----------------
__device__ __forceinline__ int edge_at(const void* ei, int idx) {
    int v;
    if (g_is64) v = (int)((const long long*)ei)[idx];
    else        v = ((const int*)ei)[idx];
    return min(max(v, 0), NN - 1);
}

// ---------------- CSR build ----------------
__global__ void k_zero(const void* ei) {
    int i = blockIdx.x * blockDim.x + threadIdx.x;
    if (i < NN) { g_cnt[i] = 0; g_fill[i] = 0; }
    if (i == 0) {   // dtype probe merged here
        const long long* p = (const long long*)ei;
        int ok = 1;
        #pragma unroll
        for (int j = 0; j < 4; j++) {
            long long v = p[j];
            if (v < 0 || v >= NN) ok = 0;
        }
        g_is64 = ok;
    }
}

__global__ void k_count(const void* __restrict__ ei) {
    int e = blockIdx.x * blockDim.x + threadIdx.x;
    if (e < EE) atomicAdd(&g_cnt[edge_at(ei, EE + e)], 1);
}

__global__ void k_scanA() {
    __shared__ int tmp[SB];
    int tid = threadIdx.x;
    int i = blockIdx.x * SB + tid;
    int v = (i < NN) ? g_cnt[i] : 0;
    tmp[tid] = v; __syncthreads();
    for (int off = 1; off < SB; off <<= 1) {
        int t = (tid >= off) ? tmp[tid - off] : 0;
        __syncthreads();
        if (tid >= off) tmp[tid] += t;
        __syncthreads();
    }
    if (i < NN) g_row[i + 1] = tmp[tid];
    if (tid == SB - 1) g_part[blockIdx.x] = tmp[tid];
}

__global__ void k_scanB() {
    __shared__ int tmp[SB];
    int tid = threadIdx.x;
    int v = (tid < NBLK) ? g_part[tid] : 0;
    tmp[tid] = v; __syncthreads();
    for (int off = 1; off < SB; off <<= 1) {
        int t = (tid >= off) ? tmp[tid - off] : 0;
        __syncthreads();
        if (tid >= off) tmp[tid] += t;
        __syncthreads();
    }
    if (tid < NBLK) g_part[tid] = tmp[tid] - v;   // exclusive block offsets
}

__global__ void k_scanC() {   // also computes g_dis (merged)
    int i = blockIdx.x * blockDim.x + threadIdx.x;
    if (i < NN) {
        g_row[i + 1] += g_part[i / SB];
        if (i == 0) g_row[0] = 0;
        g_dis[i] = rsqrtf((float)g_cnt[i] + 1.0f);
    }
}

__global__ void k_fill(const void* __restrict__ ei) {
    int e = blockIdx.x * blockDim.x + threadIdx.x;
    if (e < EE) {
        int d = edge_at(ei, EE + e);
        int s = edge_at(ei, e);
        int p = g_row[d] + atomicAdd(&g_fill[d], 1);
        g_col[p] = s;
        g_en[p] = g_dis[s] * g_dis[d];
    }
}

// ---------------- W conversion: W[k][n] fp32 -> g_Wt[layer][n][k] fp16 pairs ----------------
__global__ void k_wconv(const float* __restrict__ W2, const float* __restrict__ W3,
                        const float* __restrict__ W4, const float* __restrict__ W5) {
    int layer = blockIdx.y;
    const float* W = (layer == 0) ? W2 : (layer == 1) ? W3 : (layer == 2) ? W4 : W5;
    int KP = (layer == 0) ? 16 : 64;   // k-pairs per n
    int idx = blockIdx.x * 256 + threadIdx.x;
    if (idx < 128 * KP) {
        int n  = idx / KP;
        int kp = idx % KP;
        float lo = W[(2 * kp)     * 128 + n];
        float hi = W[(2 * kp + 1) * 128 + n];
        g_Wt[layer][n * KP + kp] = pack_f16(lo, hi);
    }
}

// ---------------- layer 1: aggregate x (2 feats) then [N,2]@[2,32]+b1, relu -> g_hB (fp16) ----------------
__global__ void k_layer1(const float* __restrict__ x,
                         const float* __restrict__ W1,
                         const float* __restrict__ b1) {
    __shared__ float w[64], bb[32];
    if (threadIdx.x < 64) w[threadIdx.x] = W1[threadIdx.x];
    if (threadIdx.x < 32) bb[threadIdx.x] = b1[threadIdx.x];
    __syncthreads();
    int v = blockIdx.x * blockDim.x + threadIdx.x;
    if (v >= NN) return;
    float dv = g_dis[v];
    float a0 = dv * dv * x[2 * v];
    float a1 = dv * dv * x[2 * v + 1];
    int e0 = g_row[v], e1 = g_row[v + 1];
    for (int e = e0; e < e1; e++) {
        int s = g_col[e];
        float nm = g_en[e];
        a0 += nm * x[2 * s];
        a1 += nm * x[2 * s + 1];
    }
    uint32_t* out = &g_hB[(size_t)v * 16];
    #pragma unroll
    for (int j = 0; j < 16; j++) {
        float r0 = fmaxf(a0 * w[2 * j]     + a1 * w[32 + 2 * j]     + bb[2 * j],     0.0f);
        float r1 = fmaxf(a0 * w[2 * j + 1] + a1 * w[32 + 2 * j + 1] + bb[2 * j + 1], 0.0f);
        out[j] = pack_f16(r0, r1);
    }
}

// ---------------- aggregation, 128 feats (fp16 rows, 256B): warp per node, unroll-4 gathers ----------------
template <bool IN_A>
__global__ void __launch_bounds__(256) k_agg128() {
    const uint32_t* hin = IN_A ? g_hA : g_hB;
    int v = blockIdx.x * 8 + (threadIdx.x >> 5);   // 25000 blocks x 8 warps = NN exactly
    int lane = threadIdx.x & 31;

    float dv = g_dis[v];
    float sn = dv * dv;
    uint2 u = __ldg((const uint2*)(hin + (size_t)v * 64) + lane);
    float2 p0 = unpack_f16(u.x), p1 = unpack_f16(u.y);
    float a0 = sn * p0.x, a1 = sn * p0.y, a2 = sn * p1.x, a3 = sn * p1.y;

    int e  = g_row[v];
    int e1 = g_row[v + 1];
    for (; e + 3 < e1; e += 4) {
        int   s0 = g_col[e],   s1 = g_col[e+1], s2 = g_col[e+2], s3 = g_col[e+3];
        float m0 = g_en[e],    m1 = g_en[e+1],  m2 = g_en[e+2],  m3 = g_en[e+3];
        uint2 u0 = __ldg((const uint2*)(hin + (size_t)s0 * 64) + lane);
        uint2 u1 = __ldg((const uint2*)(hin + (size_t)s1 * 64) + lane);
        uint2 u2 = __ldg((const uint2*)(hin + (size_t)s2 * 64) + lane);
        uint2 u3 = __ldg((const uint2*)(hin + (size_t)s3 * 64) + lane);
        float2 q;
        q = unpack_f16(u0.x); a0 += m0*q.x; a1 += m0*q.y;
        q = unpack_f16(u0.y); a2 += m0*q.x; a3 += m0*q.y;
        q = unpack_f16(u1.x); a0 += m1*q.x; a1 += m1*q.y;
        q = unpack_f16(u1.y); a2 += m1*q.x; a3 += m1*q.y;
        q = unpack_f16(u2.x); a0 += m2*q.x; a1 += m2*q.y;
        q = unpack_f16(u2.y); a2 += m2*q.x; a3 += m2*q.y;
        q = unpack_f16(u3.x); a0 += m3*q.x; a1 += m3*q.y;
        q = unpack_f16(u3.y); a2 += m3*q.x; a3 += m3*q.y;
    }
    for (; e < e1; e++) {
        int   s0 = g_col[e];
        float m0 = g_en[e];
        uint2 u0 = __ldg((const uint2*)(hin + (size_t)s0 * 64) + lane);
        float2 q;
        q = unpack_f16(u0.x); a0 += m0*q.x; a1 += m0*q.y;
        q = unpack_f16(u0.y); a2 += m0*q.x; a3 += m0*q.y;
    }

    uint2 t;
    t.x = pack_f16(a0, a1);
    t.y = pack_f16(a2, a3);
    ((uint2*)(g_hC + (size_t)v * 64))[lane] = t;
}

// ---------------- aggregation, 32 feats (fp16, 64B rows): warp per node, lanes 0..15 active ----------------
__global__ void __launch_bounds__(256) k_agg32() {
    const uint32_t* hin = g_hB;
    int v = blockIdx.x * 8 + (threadIdx.x >> 5);
    int lane = threadIdx.x & 31;
    if (lane >= 16) return;

    float dv = g_dis[v];
    float sn = dv * dv;
    float2 p = unpack_f16(__ldg(hin + (size_t)v * 16 + lane));
    float a0 = sn * p.x, a1 = sn * p.y;

    int e  = g_row[v];
    int e1 = g_row[v + 1];
    for (; e + 3 < e1; e += 4) {
        int   s0 = g_col[e],   s1 = g_col[e+1], s2 = g_col[e+2], s3 = g_col[e+3];
        float m0 = g_en[e],    m1 = g_en[e+1],  m2 = g_en[e+2],  m3 = g_en[e+3];
        float2 q0 = unpack_f16(__ldg(hin + (size_t)s0 * 16 + lane));
        float2 q1 = unpack_f16(__ldg(hin + (size_t)s1 * 16 + lane));
        float2 q2 = unpack_f16(__ldg(hin + (size_t)s2 * 16 + lane));
        float2 q3 = unpack_f16(__ldg(hin + (size_t)s3 * 16 + lane));
        a0 += m0*q0.x + m1*q1.x + m2*q2.x + m3*q3.x;
        a1 += m0*q0.y + m1*q1.y + m2*q2.y + m3*q3.y;
    }
    for (; e < e1; e++) {
        float2 q = unpack_f16(__ldg(hin + (size_t)g_col[e] * 16 + lane));
        a0 += g_en[e] * q.x;
        a1 += g_en[e] * q.y;
    }

    g_hC[(size_t)v * 16 + lane] = pack_f16(a0, a1);
}

// ---------------- GEMM: [64,FIN] fp16 (g_hC) @ [FIN,128] fp16 (g_Wt) + b, relu -> fp16 h ----------------
// 256 threads, 3125 blocks. fp16 MMA m16n8k16, fp32 accumulate.
// smem layouts (uint32 words): Ws[n][WSW] (k-pairs, transposed), As[r][ASW] (k-pairs, row-major).
// Fragment banks: A word = r*ASW + base + tig -> bank (4r+tig)%32 distinct;
//                 B word = n*WSW + base + tig -> bank (4n+tig or 20n+tig)%32 distinct.
template <int FIN, int LAYER, bool OUT_A>
__global__ void __launch_bounds__(256) k_gemm(const float* __restrict__ b) {
    constexpr int KP  = FIN / 2;        // k-pairs per row (words)
    constexpr int WSW = KP + 4;         // padded stride (words): 68 or 20
    constexpr int ASW = KP + 4;
    extern __shared__ uint32_t smU[];
    uint32_t* Ws = smU;                 // [128][WSW]
    uint32_t* As = smU + 128 * WSW;     // [64][ASW]
    uint32_t* hout = OUT_A ? g_hA : g_hB;

    const int tid  = threadIdx.x;
    const int wid  = tid >> 5;
    const int lane = tid & 31;

    // ---- copy Wt (fp16, transposed, contiguous) into padded smem ----
    {
        const uint4* Wg = (const uint4*)g_Wt[LAYER];     // [128][KP/4] uint4
        constexpr int C4 = KP / 4;                        // uint4 per n: 16 or 4
        for (int idx4 = tid; idx4 < 128 * C4; idx4 += 256) {
            int n  = idx4 / C4;
            int c4 = idx4 % C4;
            *(uint4*)&Ws[n * WSW + 4 * c4] = __ldg(&Wg[idx4]);
        }
    }

    // ---- stage A tile (64 rows, fp16) into padded smem ----
    {
        const uint4* A = (const uint4*)(g_hC + (size_t)blockIdx.x * 64 * KP);
        constexpr int C4 = KP / 4;                        // uint4 per row: 16 or 4
        for (int idx4 = tid; idx4 < 64 * C4; idx4 += 256) {
            int r  = idx4 / C4;
            int c4 = idx4 % C4;
            *(uint4*)&As[r * ASW + 4 * c4] = __ldg(&A[idx4]);
        }
    }
    __syncthreads();

    const int rowt = wid & 1;          // 2 row tiles of 32
    const int colt = wid >> 1;         // 4 col tiles of 32
    const int r_base = rowt * 32;
    const int n_base = colt * 32;
    const int group = lane >> 2;       // 0..7
    const int tig   = lane & 3;        // 0..3

    float C[2][4][4];
    #pragma unroll
    for (int mi = 0; mi < 2; mi++)
        #pragma unroll
        for (int ni = 0; ni < 4; ni++)
            #pragma unroll
            for (int j = 0; j < 4; j++) C[mi][ni][j] = 0.0f;

    #pragma unroll
    for (int kk = 0; kk < FIN; kk += 16) {
        int base = kk >> 1;            // word offset
        uint32_t a[2][4];
        #pragma unroll
        for (int mi = 0; mi < 2; mi++) {
            int r0 = r_base + mi * 16 + group;
            a[mi][0] = As[r0 * ASW + base + tig];
            a[mi][1] = As[(r0 + 8) * ASW + base + tig];
            a[mi][2] = As[r0 * ASW + base + tig + 4];
            a[mi][3] = As[(r0 + 8) * ASW + base + tig + 4];
        }
        #pragma unroll
        for (int ni = 0; ni < 4; ni++) {
            int nc = n_base + ni * 8 + group;
            uint32_t b0 = Ws[nc * WSW + base + tig];
            uint32_t b1 = Ws[nc * WSW + base + tig + 4];
            mma_f16(C[0][ni], a[0][0], a[0][1], a[0][2], a[0][3], b0, b1);
            mma_f16(C[1][ni], a[1][0], a[1][1], a[1][2], a[1][3], b0, b1);
        }
    }

    // ---- epilogue: bias + relu, pack fp16x2 ----
    #pragma unroll
    for (int ni = 0; ni < 4; ni++) {
        int col = n_base + ni * 8 + 2 * tig;
        float2 bb = __ldg((const float2*)&b[col]);
        #pragma unroll
        for (int mi = 0; mi < 2; mi++) {
            int row0 = blockIdx.x * 64 + r_base + mi * 16 + group;
            float o00 = fmaxf(C[mi][ni][0] + bb.x, 0.0f);
            float o01 = fmaxf(C[mi][ni][1] + bb.y, 0.0f);
            float o10 = fmaxf(C[mi][ni][2] + bb.x, 0.0f);
            float o11 = fmaxf(C[mi][ni][3] + bb.y, 0.0f);
            hout[(size_t)row0 * 64 + (col >> 1)]       = pack_f16(o00, o01);
            hout[(size_t)(row0 + 8) * 64 + (col >> 1)] = pack_f16(o10, o11);
        }
    }
}

// ---------------- final: out = leakyrelu(h5 @ Wl + bl), one warp per node ----------------
__global__ void k_final(const float* __restrict__ Wl,
                        const float* __restrict__ bl,
                        float* __restrict__ out) {
    int warp = (blockIdx.x * blockDim.x + threadIdx.x) >> 5;   // exactly NN warps
    int lane = threadIdx.x & 31;
    uint2 u = __ldg((const uint2*)(g_hB + (size_t)warp * 64) + lane);
    float2 p0 = unpack_f16(u.x), p1 = unpack_f16(u.y);
    float4 w  = __ldg((const float4*)&Wl[lane * 4]);
    float s = p0.x * w.x + p0.y * w.y + p1.x * w.z + p1.y * w.w;
    #pragma unroll
    for (int off = 16; off; off >>= 1) s += __shfl_down_sync(0xFFFFFFFFu, s, off);
    if (lane == 0) {
        s += __ldg(bl);
        out[warp] = (s > 0.0f) ? s : 0.01f * s;
    }
}

// ---------------- launch ----------------
extern "C" void kernel_launch(void* const* d_in, const int* in_sizes, int n_in,
                              void* d_out, int out_size) {
    int ix = 0, ie = 1, iW1 = 2, ib1 = 3, iW2 = 4, ib2 = 5, iW3 = 6, ib3 = 7,
        iW4 = 8, ib4 = 9, iW5 = 10, ib5 = 11, iWl = 12, ibl = 13;
    if (n_in >= 14 && in_sizes[0] != 2 * NN) {
        if (in_sizes[0] == 64 && in_sizes[1] == 4096) {
            iW1 = 0; iW2 = 1; iW3 = 2; iW4 = 3; iW5 = 4; iWl = 5;
            ib1 = 6; ib2 = 7; ib3 = 8; ib4 = 9; ib5 = 10; ibl = 11;
            ie = 12; ix = 13;
        }
    }

    const float* x  = (const float*)d_in[ix];
    const void*  ei = d_in[ie];
    const float* W1 = (const float*)d_in[iW1];
    const float* b1 = (const float*)d_in[ib1];
    const float* W2 = (const float*)d_in[iW2];
    const float* b2 = (const float*)d_in[ib2];
    const float* W3 = (const float*)d_in[iW3];
    const float* b3 = (const float*)d_in[ib3];
    const float* W4 = (const float*)d_in[iW4];
    const float* b4 = (const float*)d_in[ib4];
    const float* W5 = (const float*)d_in[iW5];
    const float* b5 = (const float*)d_in[ib5];
    const float* Wl = (const float*)d_in[iWl];
    const float* bl = (const float*)d_in[ibl];
    float* out = (float*)d_out;

    const int sh32  = (128 * 20 + 64 * 20) * 4;   // 15,360 B
    const int sh128 = (128 * 68 + 64 * 68) * 4;   // 52,224 B
    cudaFuncSetAttribute(k_gemm<32,  0, true >, cudaFuncAttributeMaxDynamicSharedMemorySize, sh32);
    cudaFuncSetAttribute(k_gemm<128, 1, false>, cudaFuncAttributeMaxDynamicSharedMemorySize, sh128);
    cudaFuncSetAttribute(k_gemm<128, 2, true >, cudaFuncAttributeMaxDynamicSharedMemorySize, sh128);
    cudaFuncSetAttribute(k_gemm<128, 3, false>, cudaFuncAttributeMaxDynamicSharedMemorySize, sh128);

    // CSR + norms (dtype probe merged into k_zero)
    k_zero <<<(NN + 255) / 256, 256>>>(ei);
    k_count<<<(EE + 255) / 256, 256>>>(ei);
    k_scanA<<<NBLK, SB>>>();
    k_scanB<<<1, SB>>>();
    k_scanC<<<(NN + 255) / 256, 256>>>();   // + g_dis
    k_fill <<<(EE + 255) / 256, 256>>>(ei);

    // W -> fp16 transposed, once
    k_wconv<<<dim3(32, 4), 256>>>(W2, W3, W4, W5);

    // layers: agg (fp16 gathers, fp32 accum, fp16 out) then fp16 MMA gemm (fp16 out)
    k_layer1<<<(NN + 255) / 256, 256>>>(x, W1, b1);            // x  -> hB [N,32] fp16
    k_agg32 <<<NN / 8, 256>>>();                               // hB -> C [N,32]
    k_gemm<32,  0, true ><<<3125, 256, sh32 >>>(b2);           // C  -> hA [N,128]
    k_agg128<true ><<<NN / 8, 256>>>();                        // hA -> C
    k_gemm<128, 1, false><<<3125, 256, sh128>>>(b3);           // C  -> hB
    k_agg128<false><<<NN / 8, 256>>>();                        // hB -> C
    k_gemm<128, 2, true ><<<3125, 256, sh128>>>(b4);           // C  -> hA
    k_agg128<true ><<<NN / 8, 256>>>();                        // hA -> C
    k_gemm<128, 3, false><<<3125, 256, sh128>>>(b5);           // C  -> hB

    k_final<<<NN / 8, 256>>>(Wl, bl, out);                     // 8 warps/block, exact
}

// round 9
// speedup vs baseline: 1.8544x; 1.1273x over previous
#include <cuda_runtime.h>
#include <cuda_fp16.h>
#include <cstdint>

#define NN 200000
#define EE 640000
#define SB 512
#define NBLK 391   // ceil(NN / SB)
#define ZB  782    // ceil(NN / 256)
#define G128 1563  // ceil(NN / 128)

// ---------------- persistent device scratch (no allocations allowed) ----------------
__device__ uint32_t g_hA[(size_t)NN * 64];
__device__ uint32_t g_hB[(size_t)NN * 64];
__device__ uint32_t g_hC[(size_t)NN * 64];    // aggregated rows, fp16 packed
__device__ uint32_t g_Wt[4][128 * 64];        // W2..W5 as fp16, transposed [n][k-pairs]
__device__ float    g_dis[NN];
__device__ int      g_cnt[NN];
__device__ int      g_fill[NN];
__device__ int      g_row[NN + 1];
__device__ int      g_col[EE];
__device__ float    g_en[EE];
__device__ int      g_part[SB];
__device__ int      g_is64;

// ---------------- helpers ----------------
__device__ __forceinline__ uint32_t pack_f16(float lo, float hi) {
    __half2 h = __floats2half2_rn(lo, hi);
    return *reinterpret_cast<uint32_t*>(&h);
}

__device__ __forceinline__ float2 unpack_f16(uint32_t u) {
    __half2 h = *reinterpret_cast<__half2*>(&u);
    return __half22float2(h);
}

__device__ __forceinline__ void mma_f16(float c[4],
                                        uint32_t a0, uint32_t a1, uint32_t a2, uint32_t a3,
                                        uint32_t b0, uint32_t b1) {
    asm volatile(
        "mma.sync.aligned.m16n8k16.row.col.f32.f16.f16.f32 "
        "{%0,%1,%2,%3}, {%4,%5,%6,%7}, {%8,%9}, {%0,%1,%2,%3};\n"
        : "+f"(c[0]), "+f"(c[1]), "+f"(c[2]), "+f"(c[3])
        : "r"(a0), "r"(a1), "r"(a2), "r"(a3), "r"(b0), "r"(b1));
}

__device__ __forceinline__ int edge_at(const void* ei, int idx) {
    int v;
    if (g_is64) v = (int)((const long long*)ei)[idx];
    else        v = ((const int*)ei)[idx];
    return min(max(v, 0), NN - 1);
}

// ---------------- zero + dtype probe + W conversion (merged) ----------------
__global__ void k_zero(const void* ei,
                       const float* __restrict__ W2, const float* __restrict__ W3,
                       const float* __restrict__ W4, const float* __restrict__ W5) {
    int bid = blockIdx.x;
    if (bid < ZB) {
        int i = bid * 256 + threadIdx.x;
        if (i < NN) { g_cnt[i] = 0; g_fill[i] = 0; }
        if (i == 0) {
            const long long* p = (const long long*)ei;
            int ok = 1;
            #pragma unroll
            for (int j = 0; j < 4; j++) {
                long long v = p[j];
                if (v < 0 || v >= NN) ok = 0;
            }
            g_is64 = ok;
        }
    } else {
        // W conversion: flat over 2048 (layer0) + 3*8192 (layers1-3)
        int flat = (bid - ZB) * 256 + threadIdx.x;
        int layer, idx, KP;
        if (flat < 2048) { layer = 0; idx = flat; KP = 16; }
        else             { int f2 = flat - 2048; layer = 1 + f2 / 8192; idx = f2 % 8192; KP = 64; }
        const float* W = (layer == 0) ? W2 : (layer == 1) ? W3 : (layer == 2) ? W4 : W5;
        int n  = idx / KP;
        int kp = idx % KP;
        float lo = W[(2 * kp)     * 128 + n];
        float hi = W[(2 * kp + 1) * 128 + n];
        g_Wt[layer][n * KP + kp] = pack_f16(lo, hi);
    }
}

// ---------------- CSR build ----------------
__global__ void k_count(const void* __restrict__ ei) {
    int e = blockIdx.x * blockDim.x + threadIdx.x;
    if (e < EE) atomicAdd(&g_cnt[edge_at(ei, EE + e)], 1);
}

__global__ void k_scanA() {
    __shared__ int tmp[SB];
    int tid = threadIdx.x;
    int i = blockIdx.x * SB + tid;
    int v = (i < NN) ? g_cnt[i] : 0;
    tmp[tid] = v; __syncthreads();
    for (int off = 1; off < SB; off <<= 1) {
        int t = (tid >= off) ? tmp[tid - off] : 0;
        __syncthreads();
        if (tid >= off) tmp[tid] += t;
        __syncthreads();
    }
    if (i < NN) g_row[i + 1] = tmp[tid];
    if (tid == SB - 1) g_part[blockIdx.x] = tmp[tid];
}

__global__ void k_scanB() {
    __shared__ int tmp[SB];
    int tid = threadIdx.x;
    int v = (tid < NBLK) ? g_part[tid] : 0;
    tmp[tid] = v; __syncthreads();
    for (int off = 1; off < SB; off <<= 1) {
        int t = (tid >= off) ? tmp[tid - off] : 0;
        __syncthreads();
        if (tid >= off) tmp[tid] += t;
        __syncthreads();
    }
    if (tid < NBLK) g_part[tid] = tmp[tid] - v;
}

__global__ void k_scanC() {   // + g_dis
    int i = blockIdx.x * blockDim.x + threadIdx.x;
    if (i < NN) {
        g_row[i + 1] += g_part[i / SB];
        if (i == 0) g_row[0] = 0;
        g_dis[i] = rsqrtf((float)g_cnt[i] + 1.0f);
    }
}

__global__ void k_fill(const void* __restrict__ ei) {
    int e = blockIdx.x * blockDim.x + threadIdx.x;
    if (e < EE) {
        int d = edge_at(ei, EE + e);
        int s = edge_at(ei, e);
        int p = g_row[d] + atomicAdd(&g_fill[d], 1);
        g_col[p] = s;
        g_en[p] = g_dis[s] * g_dis[d];
    }
}

// ---------------- layer 1: aggregate x (2 feats) then [N,2]@[2,32]+b1, relu -> g_hB (fp16) ----------------
__global__ void k_layer1(const float* __restrict__ x,
                         const float* __restrict__ W1,
                         const float* __restrict__ b1) {
    __shared__ float w[64], bb[32];
    if (threadIdx.x < 64) w[threadIdx.x] = W1[threadIdx.x];
    if (threadIdx.x < 32) bb[threadIdx.x] = b1[threadIdx.x];
    __syncthreads();
    int v = blockIdx.x * blockDim.x + threadIdx.x;
    if (v >= NN) return;
    float dv = g_dis[v];
    float a0 = dv * dv * x[2 * v];
    float a1 = dv * dv * x[2 * v + 1];
    int e0 = g_row[v], e1 = g_row[v + 1];
    for (int e = e0; e < e1; e++) {
        int s = g_col[e];
        float nm = g_en[e];
        a0 += nm * x[2 * s];
        a1 += nm * x[2 * s + 1];
    }
    uint32_t* out = &g_hB[(size_t)v * 16];
    #pragma unroll
    for (int j = 0; j < 16; j++) {
        float r0 = fmaxf(a0 * w[2 * j]     + a1 * w[32 + 2 * j]     + bb[2 * j],     0.0f);
        float r1 = fmaxf(a0 * w[2 * j + 1] + a1 * w[32 + 2 * j + 1] + bb[2 * j + 1], 0.0f);
        out[j] = pack_f16(r0, r1);
    }
}

// ---------------- aggregation, 128 feats (fp16 rows, 256B): warp per node ----------------
// main loop unroll-4; tail = predicated 3-slot batch (clamped idx, zero weight -> exact)
template <bool IN_A>
__global__ void __launch_bounds__(256) k_agg128() {
    const uint32_t* hin = IN_A ? g_hA : g_hB;
    int v = blockIdx.x * 8 + (threadIdx.x >> 5);   // 25000 x 8 warps = NN
    int lane = threadIdx.x & 31;

    float dv = g_dis[v];
    float sn = dv * dv;
    uint2 u = __ldg((const uint2*)(hin + (size_t)v * 64) + lane);
    float2 p0 = unpack_f16(u.x), p1 = unpack_f16(u.y);
    float a0 = sn * p0.x, a1 = sn * p0.y, a2 = sn * p1.x, a3 = sn * p1.y;

    int e  = g_row[v];
    int e1 = g_row[v + 1];
    for (; e + 3 < e1; e += 4) {
        int   s0 = g_col[e],   s1 = g_col[e+1], s2 = g_col[e+2], s3 = g_col[e+3];
        float m0 = g_en[e],    m1 = g_en[e+1],  m2 = g_en[e+2],  m3 = g_en[e+3];
        uint2 u0 = __ldg((const uint2*)(hin + (size_t)s0 * 64) + lane);
        uint2 u1 = __ldg((const uint2*)(hin + (size_t)s1 * 64) + lane);
        uint2 u2 = __ldg((const uint2*)(hin + (size_t)s2 * 64) + lane);
        uint2 u3 = __ldg((const uint2*)(hin + (size_t)s3 * 64) + lane);
        float2 q;
        q = unpack_f16(u0.x); a0 += m0*q.x; a1 += m0*q.y;
        q = unpack_f16(u0.y); a2 += m0*q.x; a3 += m0*q.y;
        q = unpack_f16(u1.x); a0 += m1*q.x; a1 += m1*q.y;
        q = unpack_f16(u1.y); a2 += m1*q.x; a3 += m1*q.y;
        q = unpack_f16(u2.x); a0 += m2*q.x; a1 += m2*q.y;
        q = unpack_f16(u2.y); a2 += m2*q.x; a3 += m2*q.y;
        q = unpack_f16(u3.x); a0 += m3*q.x; a1 += m3*q.y;
        q = unpack_f16(u3.y); a2 += m3*q.x; a3 += m3*q.y;
    }
    int rem = e1 - e;
    if (rem > 0) {
        int i1 = (rem > 1) ? e + 1 : e;
        int i2 = (rem > 2) ? e + 2 : e;
        int   s0 = g_col[e], s1 = g_col[i1], s2 = g_col[i2];
        float m0 = g_en[e];
        float m1 = (rem > 1) ? g_en[i1] : 0.0f;
        float m2 = (rem > 2) ? g_en[i2] : 0.0f;
        uint2 u0 = __ldg((const uint2*)(hin + (size_t)s0 * 64) + lane);
        uint2 u1 = __ldg((const uint2*)(hin + (size_t)s1 * 64) + lane);
        uint2 u2 = __ldg((const uint2*)(hin + (size_t)s2 * 64) + lane);
        float2 q;
        q = unpack_f16(u0.x); a0 += m0*q.x; a1 += m0*q.y;
        q = unpack_f16(u0.y); a2 += m0*q.x; a3 += m0*q.y;
        q = unpack_f16(u1.x); a0 += m1*q.x; a1 += m1*q.y;
        q = unpack_f16(u1.y); a2 += m1*q.x; a3 += m1*q.y;
        q = unpack_f16(u2.x); a0 += m2*q.x; a1 += m2*q.y;
        q = unpack_f16(u2.y); a2 += m2*q.x; a3 += m2*q.y;
    }

    uint2 t;
    t.x = pack_f16(a0, a1);
    t.y = pack_f16(a2, a3);
    ((uint2*)(g_hC + (size_t)v * 64))[lane] = t;
}

// ---------------- aggregation, 32 feats (fp16, 64B rows): warp per node, lanes 0..15 ----------------
__global__ void __launch_bounds__(256) k_agg32() {
    const uint32_t* hin = g_hB;
    int v = blockIdx.x * 8 + (threadIdx.x >> 5);
    int lane = threadIdx.x & 31;
    if (lane >= 16) return;

    float dv = g_dis[v];
    float sn = dv * dv;
    float2 p = unpack_f16(__ldg(hin + (size_t)v * 16 + lane));
    float a0 = sn * p.x, a1 = sn * p.y;

    int e  = g_row[v];
    int e1 = g_row[v + 1];
    for (; e + 3 < e1; e += 4) {
        int   s0 = g_col[e],   s1 = g_col[e+1], s2 = g_col[e+2], s3 = g_col[e+3];
        float m0 = g_en[e],    m1 = g_en[e+1],  m2 = g_en[e+2],  m3 = g_en[e+3];
        float2 q0 = unpack_f16(__ldg(hin + (size_t)s0 * 16 + lane));
        float2 q1 = unpack_f16(__ldg(hin + (size_t)s1 * 16 + lane));
        float2 q2 = unpack_f16(__ldg(hin + (size_t)s2 * 16 + lane));
        float2 q3 = unpack_f16(__ldg(hin + (size_t)s3 * 16 + lane));
        a0 += m0*q0.x + m1*q1.x + m2*q2.x + m3*q3.x;
        a1 += m0*q0.y + m1*q1.y + m2*q2.y + m3*q3.y;
    }
    int rem = e1 - e;
    if (rem > 0) {
        int i1 = (rem > 1) ? e + 1 : e;
        int i2 = (rem > 2) ? e + 2 : e;
        int   s0 = g_col[e], s1 = g_col[i1], s2 = g_col[i2];
        float m0 = g_en[e];
        float m1 = (rem > 1) ? g_en[i1] : 0.0f;
        float m2 = (rem > 2) ? g_en[i2] : 0.0f;
        float2 q0 = unpack_f16(__ldg(hin + (size_t)s0 * 16 + lane));
        float2 q1 = unpack_f16(__ldg(hin + (size_t)s1 * 16 + lane));
        float2 q2 = unpack_f16(__ldg(hin + (size_t)s2 * 16 + lane));
        a0 += m0*q0.x + m1*q1.x + m2*q2.x;
        a1 += m0*q0.y + m1*q1.y + m2*q2.y;
    }

    g_hC[(size_t)v * 16 + lane] = pack_f16(a0, a1);
}

// ---------------- GEMM: [128,FIN] fp16 (g_hC) @ [FIN,128] fp16 (g_Wt) + b ----------------
// 512 threads, G128 blocks (128 rows each, last block partial).
// OUTSEL: 0 -> hA, 1 -> hB, 2 -> fused final (dot with Wl, leaky-relu, write out).
template <int FIN, int LAYER, int OUTSEL>
__global__ void __launch_bounds__(512) k_gemm(const float* __restrict__ b,
                                              const float* __restrict__ Wl,
                                              const float* __restrict__ bl,
                                              float* __restrict__ out) {
    constexpr int KP  = FIN / 2;        // k-pair words per row
    constexpr int WSW = KP + 4;         // padded strides
    constexpr int ASW = KP + 4;
    extern __shared__ uint32_t smU[];
    uint32_t* Ws = smU;                 // [128][WSW]
    uint32_t* As = smU + 128 * WSW;     // [128][ASW]
    uint32_t* hout = (OUTSEL == 0) ? g_hA : g_hB;

    const int tid  = threadIdx.x;
    const int wid  = tid >> 5;
    const int lane = tid & 31;
    const int base_row = blockIdx.x * 128;

    // ---- copy Wt into padded smem ----
    {
        const uint4* Wg = (const uint4*)g_Wt[LAYER];
        constexpr int C4 = KP / 4;
        for (int idx4 = tid; idx4 < 128 * C4; idx4 += 512) {
            int n  = idx4 / C4;
            int c4 = idx4 % C4;
            *(uint4*)&Ws[n * WSW + 4 * c4] = __ldg(&Wg[idx4]);
        }
    }

    // ---- stage A tile (128 rows, fp16) with row clamp ----
    {
        constexpr int C4 = KP / 4;
        for (int idx4 = tid; idx4 < 128 * C4; idx4 += 512) {
            int r  = idx4 / C4;
            int c4 = idx4 % C4;
            int rg = min(base_row + r, NN - 1);
            uint4 val = __ldg((const uint4*)(g_hC + (size_t)rg * KP) + c4);
            *(uint4*)&As[r * ASW + 4 * c4] = val;
        }
    }
    __syncthreads();

    const int rowt = wid & 3;          // 4 row tiles of 32
    const int colt = wid >> 2;         // 4 col tiles of 32
    const int r_base = rowt * 32;
    const int n_base = colt * 32;
    const int group = lane >> 2;       // 0..7
    const int tig   = lane & 3;        // 0..3

    float C[2][4][4];
    #pragma unroll
    for (int mi = 0; mi < 2; mi++)
        #pragma unroll
        for (int ni = 0; ni < 4; ni++)
            #pragma unroll
            for (int j = 0; j < 4; j++) C[mi][ni][j] = 0.0f;

    #pragma unroll
    for (int kk = 0; kk < FIN; kk += 16) {
        int kbase = kk >> 1;
        uint32_t a[2][4];
        #pragma unroll
        for (int mi = 0; mi < 2; mi++) {
            int r0 = r_base + mi * 16 + group;
            a[mi][0] = As[r0 * ASW + kbase + tig];
            a[mi][1] = As[(r0 + 8) * ASW + kbase + tig];
            a[mi][2] = As[r0 * ASW + kbase + tig + 4];
            a[mi][3] = As[(r0 + 8) * ASW + kbase + tig + 4];
        }
        #pragma unroll
        for (int ni = 0; ni < 4; ni++) {
            int nc = n_base + ni * 8 + group;
            uint32_t b0 = Ws[nc * WSW + kbase + tig];
            uint32_t b1 = Ws[nc * WSW + kbase + tig + 4];
            mma_f16(C[0][ni], a[0][0], a[0][1], a[0][2], a[0][3], b0, b1);
            mma_f16(C[1][ni], a[1][0], a[1][1], a[1][2], a[1][3], b0, b1);
        }
    }

    if (OUTSEL != 2) {
        // ---- epilogue: bias + relu, pack fp16x2, guarded stores ----
        #pragma unroll
        for (int ni = 0; ni < 4; ni++) {
            int col = n_base + ni * 8 + 2 * tig;
            float2 bb = __ldg((const float2*)&b[col]);
            #pragma unroll
            for (int mi = 0; mi < 2; mi++) {
                int row0 = base_row + r_base + mi * 16 + group;
                float o00 = fmaxf(C[mi][ni][0] + bb.x, 0.0f);
                float o01 = fmaxf(C[mi][ni][1] + bb.y, 0.0f);
                float o10 = fmaxf(C[mi][ni][2] + bb.x, 0.0f);
                float o11 = fmaxf(C[mi][ni][3] + bb.y, 0.0f);
                if (row0 < NN)     hout[(size_t)row0 * 64 + (col >> 1)]       = pack_f16(o00, o01);
                if (row0 + 8 < NN) hout[(size_t)(row0 + 8) * 64 + (col >> 1)] = pack_f16(o10, o11);
            }
        }
    } else {
        // ---- fused final: rowsum = sum_col relu(C+b)*Wl[col]; out = leakyrelu(rowsum+bl) ----
        float* rowsum = (float*)As;    // reuse A smem after all warps done reading
        __syncthreads();
        if (tid < 128) rowsum[tid] = 0.0f;
        __syncthreads();
        #pragma unroll
        for (int mi = 0; mi < 2; mi++) {
            #pragma unroll
            for (int half = 0; half < 2; half++) {
                float partial = 0.0f;
                #pragma unroll
                for (int ni = 0; ni < 4; ni++) {
                    int col = n_base + ni * 8 + 2 * tig;
                    float2 bb = __ldg((const float2*)&b[col]);
                    float v0 = fmaxf(C[mi][ni][2 * half]     + bb.x, 0.0f);
                    float v1 = fmaxf(C[mi][ni][2 * half + 1] + bb.y, 0.0f);
                    float2 wl = __ldg((const float2*)&Wl[col]);
                    partial += v0 * wl.x + v1 * wl.y;
                }
                partial += __shfl_xor_sync(0xFFFFFFFFu, partial, 1);
                partial += __shfl_xor_sync(0xFFFFFFFFu, partial, 2);
                if (tig == 0) {
                    int rloc = r_base + mi * 16 + group + 8 * half;
                    atomicAdd(&rowsum[rloc], partial);
                }
            }
        }
        __syncthreads();
        if (tid < 128) {
            int row = base_row + tid;
            if (row < NN) {
                float s = rowsum[tid] + __ldg(bl);
                out[row] = (s > 0.0f) ? s : 0.01f * s;
            }
        }
    }
}

// ---------------- launch ----------------
extern "C" void kernel_launch(void* const* d_in, const int* in_sizes, int n_in,
                              void* d_out, int out_size) {
    int ix = 0, ie = 1, iW1 = 2, ib1 = 3, iW2 = 4, ib2 = 5, iW3 = 6, ib3 = 7,
        iW4 = 8, ib4 = 9, iW5 = 10, ib5 = 11, iWl = 12, ibl = 13;
    if (n_in >= 14 && in_sizes[0] != 2 * NN) {
        if (in_sizes[0] == 64 && in_sizes[1] == 4096) {
            iW1 = 0; iW2 = 1; iW3 = 2; iW4 = 3; iW5 = 4; iWl = 5;
            ib1 = 6; ib2 = 7; ib3 = 8; ib4 = 9; ib5 = 10; ibl = 11;
            ie = 12; ix = 13;
        }
    }

    const float* x  = (const float*)d_in[ix];
    const void*  ei = d_in[ie];
    const float* W1 = (const float*)d_in[iW1];
    const float* b1 = (const float*)d_in[ib1];
    const float* W2 = (const float*)d_in[iW2];
    const float* b2 = (const float*)d_in[ib2];
    const float* W3 = (const float*)d_in[iW3];
    const float* b3 = (const float*)d_in[ib3];
    const float* W4 = (const float*)d_in[iW4];
    const float* b4 = (const float*)d_in[ib4];
    const float* W5 = (const float*)d_in[iW5];
    const float* b5 = (const float*)d_in[ib5];
    const float* Wl = (const float*)d_in[iWl];
    const float* bl = (const float*)d_in[ibl];
    float* out = (float*)d_out;

    const int sh32  = (128 * 20 + 128 * 20) * 4;   // 20,480 B
    const int sh128 = (128 * 68 + 128 * 68) * 4;   // 69,632 B
    cudaFuncSetAttribute(k_gemm<32,  0, 0>, cudaFuncAttributeMaxDynamicSharedMemorySize, sh32);
    cudaFuncSetAttribute(k_gemm<128, 1, 1>, cudaFuncAttributeMaxDynamicSharedMemorySize, sh128);
    cudaFuncSetAttribute(k_gemm<128, 2, 0>, cudaFuncAttributeMaxDynamicSharedMemorySize, sh128);
    cudaFuncSetAttribute(k_gemm<128, 3, 2>, cudaFuncAttributeMaxDynamicSharedMemorySize, sh128);

    // CSR + norms + W conversion (zero/probe/wconv merged)
    k_zero <<<ZB + 104, 256>>>(ei, W2, W3, W4, W5);
    k_count<<<(EE + 255) / 256, 256>>>(ei);
    k_scanA<<<NBLK, SB>>>();
    k_scanB<<<1, SB>>>();
    k_scanC<<<(NN + 255) / 256, 256>>>();
    k_fill <<<(EE + 255) / 256, 256>>>(ei);

    // layers
    k_layer1<<<(NN + 255) / 256, 256>>>(x, W1, b1);            // x  -> hB [N,32] fp16
    k_agg32 <<<NN / 8, 256>>>();                               // hB -> C
    k_gemm<32,  0, 0><<<G128, 512, sh32 >>>(b2, Wl, bl, out);  // C  -> hA
    k_agg128<true ><<<NN / 8, 256>>>();                        // hA -> C
    k_gemm<128, 1, 1><<<G128, 512, sh128>>>(b3, Wl, bl, out);  // C  -> hB
    k_agg128<false><<<NN / 8, 256>>>();                        // hB -> C
    k_gemm<128, 2, 0><<<G128, 512, sh128>>>(b4, Wl, bl, out);  // C  -> hA
    k_agg128<true ><<<NN / 8, 256>>>();                        // hA -> C
    k_gemm<128, 3, 2><<<G128, 512, sh128>>>(b5, Wl, bl, out);  // C  -> out (fused final)
}

// round 10
// speedup vs baseline: 2.0233x; 1.0911x over previous
#include <cuda_runtime.h>
#include <cuda_fp16.h>
#include <cstdint>

#define NN 200000
#define EE 640000
#define SB 512
#define NBLK 391   // ceil(NN / SB)
#define ZB  782    // ceil(NN / 256)
#define G128 1563  // ceil(NN / 128)

// ---------------- persistent device scratch (no allocations allowed) ----------------
__device__ uint32_t g_hA[(size_t)NN * 64];
__device__ uint32_t g_hB[(size_t)NN * 64];
__device__ uint32_t g_hC[(size_t)NN * 64];    // aggregated rows, fp16 packed
__device__ uint32_t g_Wt[4][128 * 64];        // W2..W5 as fp16, transposed [n][k-pairs]
__device__ float    g_dis[NN];
__device__ int      g_cnt[NN];
__device__ int      g_fill[NN];
__device__ int      g_row[NN + 1];
__device__ uint2    g_ce[EE];                 // packed {col, norm bits}
__device__ int      g_part[SB];
__device__ int      g_is64;

// ---------------- helpers ----------------
__device__ __forceinline__ uint32_t pack_f16(float lo, float hi) {
    __half2 h = __floats2half2_rn(lo, hi);
    return *reinterpret_cast<uint32_t*>(&h);
}

__device__ __forceinline__ float2 unpack_f16(uint32_t u) {
    __half2 h = *reinterpret_cast<__half2*>(&u);
    return __half22float2(h);
}

__device__ __forceinline__ void mma_f16(float c[4],
                                        uint32_t a0, uint32_t a1, uint32_t a2, uint32_t a3,
                                        uint32_t b0, uint32_t b1) {
    asm volatile(
        "mma.sync.aligned.m16n8k16.row.col.f32.f16.f16.f32 "
        "{%0,%1,%2,%3}, {%4,%5,%6,%7}, {%8,%9}, {%0,%1,%2,%3};\n"
        : "+f"(c[0]), "+f"(c[1]), "+f"(c[2]), "+f"(c[3])
        : "r"(a0), "r"(a1), "r"(a2), "r"(a3), "r"(b0), "r"(b1));
}

__device__ __forceinline__ int edge_at(const void* ei, int idx) {
    int v;
    if (g_is64) v = (int)((const long long*)ei)[idx];
    else        v = ((const int*)ei)[idx];
    return min(max(v, 0), NN - 1);
}

// ---------------- zero + dtype probe + W conversion (merged) ----------------
__global__ void k_zero(const void* ei,
                       const float* __restrict__ W2, const float* __restrict__ W3,
                       const float* __restrict__ W4, const float* __restrict__ W5) {
    int bid = blockIdx.x;
    if (bid < ZB) {
        int i = bid * 256 + threadIdx.x;
        if (i < NN) { g_cnt[i] = 0; g_fill[i] = 0; }
        if (i == 0) {
            const long long* p = (const long long*)ei;
            int ok = 1;
            #pragma unroll
            for (int j = 0; j < 4; j++) {
                long long v = p[j];
                if (v < 0 || v >= NN) ok = 0;
            }
            g_is64 = ok;
        }
    } else {
        int flat = (bid - ZB) * 256 + threadIdx.x;
        int layer, idx, KP;
        if (flat < 2048) { layer = 0; idx = flat; KP = 16; }
        else             { int f2 = flat - 2048; layer = 1 + f2 / 8192; idx = f2 % 8192; KP = 64; }
        const float* W = (layer == 0) ? W2 : (layer == 1) ? W3 : (layer == 2) ? W4 : W5;
        int n  = idx / KP;
        int kp = idx % KP;
        float lo = W[(2 * kp)     * 128 + n];
        float hi = W[(2 * kp + 1) * 128 + n];
        g_Wt[layer][n * KP + kp] = pack_f16(lo, hi);
    }
}

// ---------------- CSR build ----------------
__global__ void k_count(const void* __restrict__ ei) {
    int e = blockIdx.x * blockDim.x + threadIdx.x;
    if (e < EE) atomicAdd(&g_cnt[edge_at(ei, EE + e)], 1);
}

__global__ void k_scanA() {
    __shared__ int tmp[SB];
    int tid = threadIdx.x;
    int i = blockIdx.x * SB + tid;
    int v = (i < NN) ? g_cnt[i] : 0;
    tmp[tid] = v; __syncthreads();
    for (int off = 1; off < SB; off <<= 1) {
        int t = (tid >= off) ? tmp[tid - off] : 0;
        __syncthreads();
        if (tid >= off) tmp[tid] += t;
        __syncthreads();
    }
    if (i < NN) g_row[i + 1] = tmp[tid];
    if (tid == SB - 1) g_part[blockIdx.x] = tmp[tid];
}

__global__ void k_scanB() {
    __shared__ int tmp[SB];
    int tid = threadIdx.x;
    int v = (tid < NBLK) ? g_part[tid] : 0;
    tmp[tid] = v; __syncthreads();
    for (int off = 1; off < SB; off <<= 1) {
        int t = (tid >= off) ? tmp[tid - off] : 0;
        __syncthreads();
        if (tid >= off) tmp[tid] += t;
        __syncthreads();
    }
    if (tid < NBLK) g_part[tid] = tmp[tid] - v;
}

__global__ void k_scanC() {   // + g_dis
    int i = blockIdx.x * blockDim.x + threadIdx.x;
    if (i < NN) {
        g_row[i + 1] += g_part[i / SB];
        if (i == 0) g_row[0] = 0;
        g_dis[i] = rsqrtf((float)g_cnt[i] + 1.0f);
    }
}

__global__ void k_fill(const void* __restrict__ ei) {
    int e = blockIdx.x * blockDim.x + threadIdx.x;
    if (e < EE) {
        int d = edge_at(ei, EE + e);
        int s = edge_at(ei, e);
        int p = g_row[d] + atomicAdd(&g_fill[d], 1);
        g_ce[p] = make_uint2((uint32_t)s, __float_as_uint(g_dis[s] * g_dis[d]));
    }
}

// ---------------- layer 1: aggregate x (2 feats) then [N,2]@[2,32]+b1, relu -> g_hB (fp16) ----------------
__global__ void k_layer1(const float* __restrict__ x,
                         const float* __restrict__ W1,
                         const float* __restrict__ b1) {
    __shared__ float w[64], bb[32];
    if (threadIdx.x < 64) w[threadIdx.x] = W1[threadIdx.x];
    if (threadIdx.x < 32) bb[threadIdx.x] = b1[threadIdx.x];
    __syncthreads();
    int v = blockIdx.x * blockDim.x + threadIdx.x;
    if (v >= NN) return;
    float dv = g_dis[v];
    float a0 = dv * dv * x[2 * v];
    float a1 = dv * dv * x[2 * v + 1];
    int e0 = g_row[v], e1 = g_row[v + 1];
    for (int e = e0; e < e1; e++) {
        uint2 ce = g_ce[e];
        int s = (int)ce.x;
        float nm = __uint_as_float(ce.y);
        a0 += nm * x[2 * s];
        a1 += nm * x[2 * s + 1];
    }
    uint32_t* out = &g_hB[(size_t)v * 16];
    #pragma unroll
    for (int j = 0; j < 16; j++) {
        float r0 = fmaxf(a0 * w[2 * j]     + a1 * w[32 + 2 * j]     + bb[2 * j],     0.0f);
        float r1 = fmaxf(a0 * w[2 * j + 1] + a1 * w[32 + 2 * j + 1] + bb[2 * j + 1], 0.0f);
        out[j] = pack_f16(r0, r1);
    }
}

// ---------------- aggregation, 128 feats: 16 lanes per node (uint4 = 256B row), 2 nodes/warp ----------------
// main loop unroll-2; tail = predicated 3-slot batch (clamped idx, zero weight -> exact)
template <bool IN_A>
__global__ void __launch_bounds__(256) k_agg128() {
    const uint32_t* hin = IN_A ? g_hA : g_hB;
    int v = blockIdx.x * 16 + (threadIdx.x >> 4);   // 12500 blocks x 16 nodes = NN
    int l = threadIdx.x & 15;

    float dv = g_dis[v];
    float sn = dv * dv;
    uint4 u = __ldg((const uint4*)(hin + (size_t)v * 64) + l);
    float2 p0 = unpack_f16(u.x), p1 = unpack_f16(u.y), p2 = unpack_f16(u.z), p3 = unpack_f16(u.w);
    float a0 = sn*p0.x, a1 = sn*p0.y, a2 = sn*p1.x, a3 = sn*p1.y;
    float a4 = sn*p2.x, a5 = sn*p2.y, a6 = sn*p3.x, a7 = sn*p3.y;

    int e  = g_row[v];
    int e1 = g_row[v + 1];
    for (; e + 1 < e1 - 3 + 3; e += 2) {     // pairs while >= 2 left beyond what tail handles
        if (e + 1 >= e1) break;
        if (e1 - e <= 3) break;              // leave <=3 for the batched tail
        uint2 c0 = __ldg(&g_ce[e]);
        uint2 c1 = __ldg(&g_ce[e + 1]);
        float m0 = __uint_as_float(c0.y), m1 = __uint_as_float(c1.y);
        uint4 u0 = __ldg((const uint4*)(hin + (size_t)c0.x * 64) + l);
        uint4 u1 = __ldg((const uint4*)(hin + (size_t)c1.x * 64) + l);
        float2 q;
        q = unpack_f16(u0.x); a0 += m0*q.x; a1 += m0*q.y;
        q = unpack_f16(u0.y); a2 += m0*q.x; a3 += m0*q.y;
        q = unpack_f16(u0.z); a4 += m0*q.x; a5 += m0*q.y;
        q = unpack_f16(u0.w); a6 += m0*q.x; a7 += m0*q.y;
        q = unpack_f16(u1.x); a0 += m1*q.x; a1 += m1*q.y;
        q = unpack_f16(u1.y); a2 += m1*q.x; a3 += m1*q.y;
        q = unpack_f16(u1.z); a4 += m1*q.x; a5 += m1*q.y;
        q = unpack_f16(u1.w); a6 += m1*q.x; a7 += m1*q.y;
    }
    int rem = e1 - e;
    if (rem > 0) {
        int i1 = (rem > 1) ? e + 1 : e;
        int i2 = (rem > 2) ? e + 2 : e;
        uint2 c0 = __ldg(&g_ce[e]);
        uint2 c1 = __ldg(&g_ce[i1]);
        uint2 c2 = __ldg(&g_ce[i2]);
        float m0 = __uint_as_float(c0.y);
        float m1 = (rem > 1) ? __uint_as_float(c1.y) : 0.0f;
        float m2 = (rem > 2) ? __uint_as_float(c2.y) : 0.0f;
        uint4 u0 = __ldg((const uint4*)(hin + (size_t)c0.x * 64) + l);
        uint4 u1 = __ldg((const uint4*)(hin + (size_t)c1.x * 64) + l);
        uint4 u2 = __ldg((const uint4*)(hin + (size_t)c2.x * 64) + l);
        float2 q;
        q = unpack_f16(u0.x); a0 += m0*q.x; a1 += m0*q.y;
        q = unpack_f16(u0.y); a2 += m0*q.x; a3 += m0*q.y;
        q = unpack_f16(u0.z); a4 += m0*q.x; a5 += m0*q.y;
        q = unpack_f16(u0.w); a6 += m0*q.x; a7 += m0*q.y;
        q = unpack_f16(u1.x); a0 += m1*q.x; a1 += m1*q.y;
        q = unpack_f16(u1.y); a2 += m1*q.x; a3 += m1*q.y;
        q = unpack_f16(u1.z); a4 += m1*q.x; a5 += m1*q.y;
        q = unpack_f16(u1.w); a6 += m1*q.x; a7 += m1*q.y;
        q = unpack_f16(u2.x); a0 += m2*q.x; a1 += m2*q.y;
        q = unpack_f16(u2.y); a2 += m2*q.x; a3 += m2*q.y;
        q = unpack_f16(u2.z); a4 += m2*q.x; a5 += m2*q.y;
        q = unpack_f16(u2.w); a6 += m2*q.x; a7 += m2*q.y;
    }

    uint4 t;
    t.x = pack_f16(a0, a1); t.y = pack_f16(a2, a3);
    t.z = pack_f16(a4, a5); t.w = pack_f16(a6, a7);
    ((uint4*)(g_hC + (size_t)v * 64))[l] = t;
}

// ---------------- aggregation, 32 feats: 16 lanes per node (uint32 = 64B row), 2 nodes/warp ----------------
__global__ void __launch_bounds__(256) k_agg32() {
    const uint32_t* hin = g_hB;
    int v = blockIdx.x * 16 + (threadIdx.x >> 4);   // 12500 blocks
    int l = threadIdx.x & 15;

    float dv = g_dis[v];
    float sn = dv * dv;
    float2 p = unpack_f16(__ldg(hin + (size_t)v * 16 + l));
    float a0 = sn * p.x, a1 = sn * p.y;

    int e  = g_row[v];
    int e1 = g_row[v + 1];
    for (; e1 - e > 3; e += 2) {
        uint2 c0 = __ldg(&g_ce[e]);
        uint2 c1 = __ldg(&g_ce[e + 1]);
        float m0 = __uint_as_float(c0.y), m1 = __uint_as_float(c1.y);
        float2 q0 = unpack_f16(__ldg(hin + (size_t)c0.x * 16 + l));
        float2 q1 = unpack_f16(__ldg(hin + (size_t)c1.x * 16 + l));
        a0 += m0*q0.x + m1*q1.x;
        a1 += m0*q0.y + m1*q1.y;
    }
    int rem = e1 - e;
    if (rem > 0) {
        int i1 = (rem > 1) ? e + 1 : e;
        int i2 = (rem > 2) ? e + 2 : e;
        uint2 c0 = __ldg(&g_ce[e]);
        uint2 c1 = __ldg(&g_ce[i1]);
        uint2 c2 = __ldg(&g_ce[i2]);
        float m0 = __uint_as_float(c0.y);
        float m1 = (rem > 1) ? __uint_as_float(c1.y) : 0.0f;
        float m2 = (rem > 2) ? __uint_as_float(c2.y) : 0.0f;
        float2 q0 = unpack_f16(__ldg(hin + (size_t)c0.x * 16 + l));
        float2 q1 = unpack_f16(__ldg(hin + (size_t)c1.x * 16 + l));
        float2 q2 = unpack_f16(__ldg(hin + (size_t)c2.x * 16 + l));
        a0 += m0*q0.x + m1*q1.x + m2*q2.x;
        a1 += m0*q0.y + m1*q1.y + m2*q2.y;
    }

    g_hC[(size_t)v * 16 + l] = pack_f16(a0, a1);
}

// ---------------- GEMM: [128,FIN] fp16 (g_hC) @ [FIN,128] fp16 (g_Wt) + b ----------------
// 512 threads, G128 blocks. OUTSEL: 0 -> hA, 1 -> hB, 2 -> fused final.
template <int FIN, int LAYER, int OUTSEL>
__global__ void __launch_bounds__(512) k_gemm(const float* __restrict__ b,
                                              const float* __restrict__ Wl,
                                              const float* __restrict__ bl,
                                              float* __restrict__ out) {
    constexpr int KP  = FIN / 2;
    constexpr int WSW = KP + 4;
    constexpr int ASW = KP + 4;
    extern __shared__ uint32_t smU[];
    uint32_t* Ws = smU;                 // [128][WSW]
    uint32_t* As = smU + 128 * WSW;     // [128][ASW]
    uint32_t* hout = (OUTSEL == 0) ? g_hA : g_hB;

    const int tid  = threadIdx.x;
    const int wid  = tid >> 5;
    const int lane = tid & 31;
    const int base_row = blockIdx.x * 128;

    {
        const uint4* Wg = (const uint4*)g_Wt[LAYER];
        constexpr int C4 = KP / 4;
        for (int idx4 = tid; idx4 < 128 * C4; idx4 += 512) {
            int n  = idx4 / C4;
            int c4 = idx4 % C4;
            *(uint4*)&Ws[n * WSW + 4 * c4] = __ldg(&Wg[idx4]);
        }
    }
    {
        constexpr int C4 = KP / 4;
        for (int idx4 = tid; idx4 < 128 * C4; idx4 += 512) {
            int r  = idx4 / C4;
            int c4 = idx4 % C4;
            int rg = min(base_row + r, NN - 1);
            uint4 val = __ldg((const uint4*)(g_hC + (size_t)rg * KP) + c4);
            *(uint4*)&As[r * ASW + 4 * c4] = val;
        }
    }
    __syncthreads();

    const int rowt = wid & 3;
    const int colt = wid >> 2;
    const int r_base = rowt * 32;
    const int n_base = colt * 32;
    const int group = lane >> 2;
    const int tig   = lane & 3;

    float C[2][4][4];
    #pragma unroll
    for (int mi = 0; mi < 2; mi++)
        #pragma unroll
        for (int ni = 0; ni < 4; ni++)
            #pragma unroll
            for (int j = 0; j < 4; j++) C[mi][ni][j] = 0.0f;

    #pragma unroll
    for (int kk = 0; kk < FIN; kk += 16) {
        int kbase = kk >> 1;
        uint32_t a[2][4];
        #pragma unroll
        for (int mi = 0; mi < 2; mi++) {
            int r0 = r_base + mi * 16 + group;
            a[mi][0] = As[r0 * ASW + kbase + tig];
            a[mi][1] = As[(r0 + 8) * ASW + kbase + tig];
            a[mi][2] = As[r0 * ASW + kbase + tig + 4];
            a[mi][3] = As[(r0 + 8) * ASW + kbase + tig + 4];
        }
        #pragma unroll
        for (int ni = 0; ni < 4; ni++) {
            int nc = n_base + ni * 8 + group;
            uint32_t b0 = Ws[nc * WSW + kbase + tig];
            uint32_t b1 = Ws[nc * WSW + kbase + tig + 4];
            mma_f16(C[0][ni], a[0][0], a[0][1], a[0][2], a[0][3], b0, b1);
            mma_f16(C[1][ni], a[1][0], a[1][1], a[1][2], a[1][3], b0, b1);
        }
    }

    if (OUTSEL != 2) {
        #pragma unroll
        for (int ni = 0; ni < 4; ni++) {
            int col = n_base + ni * 8 + 2 * tig;
            float2 bb = __ldg((const float2*)&b[col]);
            #pragma unroll
            for (int mi = 0; mi < 2; mi++) {
                int row0 = base_row + r_base + mi * 16 + group;
                float o00 = fmaxf(C[mi][ni][0] + bb.x, 0.0f);
                float o01 = fmaxf(C[mi][ni][1] + bb.y, 0.0f);
                float o10 = fmaxf(C[mi][ni][2] + bb.x, 0.0f);
                float o11 = fmaxf(C[mi][ni][3] + bb.y, 0.0f);
                if (row0 < NN)     hout[(size_t)row0 * 64 + (col >> 1)]       = pack_f16(o00, o01);
                if (row0 + 8 < NN) hout[(size_t)(row0 + 8) * 64 + (col >> 1)] = pack_f16(o10, o11);
            }
        }
    } else {
        float* rowsum = (float*)As;
        __syncthreads();
        if (tid < 128) rowsum[tid] = 0.0f;
        __syncthreads();
        #pragma unroll
        for (int mi = 0; mi < 2; mi++) {
            #pragma unroll
            for (int half = 0; half < 2; half++) {
                float partial = 0.0f;
                #pragma unroll
                for (int ni = 0; ni < 4; ni++) {
                    int col = n_base + ni * 8 + 2 * tig;
                    float2 bb = __ldg((const float2*)&b[col]);
                    float v0 = fmaxf(C[mi][ni][2 * half]     + bb.x, 0.0f);
                    float v1 = fmaxf(C[mi][ni][2 * half + 1] + bb.y, 0.0f);
                    float2 wl = __ldg((const float2*)&Wl[col]);
                    partial += v0 * wl.x + v1 * wl.y;
                }
                partial += __shfl_xor_sync(0xFFFFFFFFu, partial, 1);
                partial += __shfl_xor_sync(0xFFFFFFFFu, partial, 2);
                if (tig == 0) {
                    int rloc = r_base + mi * 16 + group + 8 * half;
                    atomicAdd(&rowsum[rloc], partial);
                }
            }
        }
        __syncthreads();
        if (tid < 128) {
            int row = base_row + tid;
            if (row < NN) {
                float s = rowsum[tid] + __ldg(bl);
                out[row] = (s > 0.0f) ? s : 0.01f * s;
            }
        }
    }
}

// ---------------- launch ----------------
extern "C" void kernel_launch(void* const* d_in, const int* in_sizes, int n_in,
                              void* d_out, int out_size) {
    int ix = 0, ie = 1, iW1 = 2, ib1 = 3, iW2 = 4, ib2 = 5, iW3 = 6, ib3 = 7,
        iW4 = 8, ib4 = 9, iW5 = 10, ib5 = 11, iWl = 12, ibl = 13;
    if (n_in >= 14 && in_sizes[0] != 2 * NN) {
        if (in_sizes[0] == 64 && in_sizes[1] == 4096) {
            iW1 = 0; iW2 = 1; iW3 = 2; iW4 = 3; iW5 = 4; iWl = 5;
            ib1 = 6; ib2 = 7; ib3 = 8; ib4 = 9; ib5 = 10; ibl = 11;
            ie = 12; ix = 13;
        }
    }

    const float* x  = (const float*)d_in[ix];
    const void*  ei = d_in[ie];
    const float* W1 = (const float*)d_in[iW1];
    const float* b1 = (const float*)d_in[ib1];
    const float* W2 = (const float*)d_in[iW2];
    const float* b2 = (const float*)d_in[ib2];
    const float* W3 = (const float*)d_in[iW3];
    const float* b3 = (const float*)d_in[ib3];
    const float* W4 = (const float*)d_in[iW4];
    const float* b4 = (const float*)d_in[ib4];
    const float* W5 = (const float*)d_in[iW5];
    const float* b5 = (const float*)d_in[ib5];
    const float* Wl = (const float*)d_in[iWl];
    const float* bl = (const float*)d_in[ibl];
    float* out = (float*)d_out;

    const int sh32  = (128 * 20 + 128 * 20) * 4;   // 20,480 B
    const int sh128 = (128 * 68 + 128 * 68) * 4;   // 69,632 B
    cudaFuncSetAttribute(k_gemm<32,  0, 0>, cudaFuncAttributeMaxDynamicSharedMemorySize, sh32);
    cudaFuncSetAttribute(k_gemm<128, 1, 1>, cudaFuncAttributeMaxDynamicSharedMemorySize, sh128);
    cudaFuncSetAttribute(k_gemm<128, 2, 0>, cudaFuncAttributeMaxDynamicSharedMemorySize, sh128);
    cudaFuncSetAttribute(k_gemm<128, 3, 2>, cudaFuncAttributeMaxDynamicSharedMemorySize, sh128);

    // CSR + norms + W conversion
    k_zero <<<ZB + 104, 256>>>(ei, W2, W3, W4, W5);
    k_count<<<(EE + 255) / 256, 256>>>(ei);
    k_scanA<<<NBLK, SB>>>();
    k_scanB<<<1, SB>>>();
    k_scanC<<<(NN + 255) / 256, 256>>>();
    k_fill <<<(EE + 255) / 256, 256>>>(ei);

    // layers
    k_layer1<<<(NN + 255) / 256, 256>>>(x, W1, b1);            // x  -> hB [N,32] fp16
    k_agg32 <<<NN / 16, 256>>>();                              // hB -> C
    k_gemm<32,  0, 0><<<G128, 512, sh32 >>>(b2, Wl, bl, out);  // C  -> hA
    k_agg128<true ><<<NN / 16, 256>>>();                       // hA -> C
    k_gemm<128, 1, 1><<<G128, 512, sh128>>>(b3, Wl, bl, out);  // C  -> hB
    k_agg128<false><<<NN / 16, 256>>>();                       // hB -> C
    k_gemm<128, 2, 0><<<G128, 512, sh128>>>(b4, Wl, bl, out);  // C  -> hA
    k_agg128<true ><<<NN / 16, 256>>>();                       // hA -> C
    k_gemm<128, 3, 2><<<G128, 512, sh128>>>(b5, Wl, bl, out);  // C  -> out (fused final)
}